// round 14
// baseline (speedup 1.0000x reference)
#include <cuda_runtime.h>
#include <cuda_fp16.h>
#include <cstdint>
#include <cstddef>

#define BB 32
#define SS 576
#define DD 768
#define HH 12
#define HDD 64
#define MTOK (BB*SS)               // 18432
#define OUT_ELEMS (BB*SS*DD)       // 14155776
#define ATTN_ELEMS (BB*HH*SS*SS)   // 127401984
#define SCALE 0.125f

// ---- scratch (static device globals; no runtime allocation) ----
__device__ float g_q[OUT_ELEMS];
__device__ float g_k[OUT_ELEMS];
__device__ __half g_vt[OUT_ELEMS];   // V fp16, transposed: [b][h][dim][token]
__device__ float g_ctx[OUT_ELEMS];
__device__ float g_xr[OUT_ELEMS];
__device__ float g_wq[DD*DD], g_wk[DD*DD], g_wv[DD*DD], g_wo[DD*DD];
__device__ float g_attn_fallback[ATTN_ELEMS];

// ---------------------------------------------------------------------------
__device__ __forceinline__ float rna_tf32(float x) {
    unsigned u;
    asm("cvt.rna.tf32.f32 %0, %1;" : "=r"(u) : "f"(x));
    return __uint_as_float(u);
}

__device__ __forceinline__ void mma_tf32(float c[4],
    uint32_t a0, uint32_t a1, uint32_t a2, uint32_t a3,
    uint32_t b0, uint32_t b1)
{
    asm volatile(
        "mma.sync.aligned.m16n8k8.row.col.f32.tf32.tf32.f32 "
        "{%0,%1,%2,%3}, {%4,%5,%6,%7}, {%8,%9}, {%0,%1,%2,%3};"
        : "+f"(c[0]), "+f"(c[1]), "+f"(c[2]), "+f"(c[3])
        : "r"(a0), "r"(a1), "r"(a2), "r"(a3), "r"(b0), "r"(b1));
}

__device__ __forceinline__ void mma_f16(float c[4],
    uint32_t a0, uint32_t a1, uint32_t a2, uint32_t a3,
    uint32_t b0, uint32_t b1)
{
    asm volatile(
        "mma.sync.aligned.m16n8k16.row.col.f32.f16.f16.f32 "
        "{%0,%1,%2,%3}, {%4,%5,%6,%7}, {%8,%9}, {%0,%1,%2,%3};"
        : "+f"(c[0]), "+f"(c[1]), "+f"(c[2]), "+f"(c[3])
        : "r"(a0), "r"(a1), "r"(a2), "r"(a3), "r"(b0), "r"(b1));
}

__device__ __forceinline__ void ldsm_x4(uint32_t& r0, uint32_t& r1,
                                        uint32_t& r2, uint32_t& r3,
                                        const void* p)
{
    uint32_t a = (uint32_t)__cvta_generic_to_shared(p);
    asm volatile("ldmatrix.sync.aligned.m8n8.x4.shared.b16 {%0,%1,%2,%3}, [%4];"
                 : "=r"(r0), "=r"(r1), "=r"(r2), "=r"(r3) : "r"(a));
}

__device__ __forceinline__ void cpa16(void* dst, const void* src) {
    uint32_t d = (uint32_t)__cvta_generic_to_shared(dst);
    asm volatile("cp.async.cg.shared.global [%0], [%1], 16;\n"
                 :: "r"(d), "l"(src));
}
#define CP_COMMIT() asm volatile("cp.async.commit_group;\n" ::)
#define CP_WAIT1()  asm volatile("cp.async.wait_group 1;\n" ::)
#define CP_WAIT2()  asm volatile("cp.async.wait_group 2;\n" ::)

// ---------------------------------------------------------------------------
__global__ void round_tf32_kernel(const float* __restrict__ in,
                                  float* __restrict__ out, int n4)
{
    for (int i = blockIdx.x * blockDim.x + threadIdx.x; i < n4;
         i += gridDim.x * blockDim.x) {
        float4 v = ((const float4*)in)[i];
        v.x = rna_tf32(v.x); v.y = rna_tf32(v.y);
        v.z = rna_tf32(v.z); v.w = rna_tf32(v.w);
        ((float4*)out)[i] = v;
    }
}

__global__ void round_w4_kernel(
    const float* __restrict__ w0, const float* __restrict__ w1,
    const float* __restrict__ w2, const float* __restrict__ w3,
    float* __restrict__ o0, float* __restrict__ o1,
    float* __restrict__ o2, float* __restrict__ o3, int n4)
{
    int z = blockIdx.y;
    const float* in = (z == 0) ? w0 : (z == 1) ? w1 : (z == 2) ? w2 : w3;
    float* out      = (z == 0) ? o0 : (z == 1) ? o1 : (z == 2) ? o2 : o3;
    for (int i = blockIdx.x * blockDim.x + threadIdx.x; i < n4;
         i += gridDim.x * blockDim.x) {
        float4 v = ((const float4*)in)[i];
        v.x = rna_tf32(v.x); v.y = rna_tf32(v.y);
        v.z = rna_tf32(v.z); v.w = rna_tf32(v.w);
        ((float4*)out)[i] = v;
    }
}

// ---------------------------------------------------------------------------
// GEMM: C[M,N] = A[M,K] @ W^T + bias.  A,W pre-rounded to tf32.
// MODE 0: plain fp32 store.  MODE 1: rna-rounded fp32 store (Q,K).
// MODE 2: fp16 transposed store into VT[b][h][dim][token] (V).
// BM=128, BN=128, BK=32, 256 threads, ldmatrix frags (double-buffered),
// 3-stage cp.async pipeline, one __syncthreads per iteration.
// ---------------------------------------------------------------------------
#define GST (2*128*36)   // floats per stage (A+B)

template <int MODE>
__device__ __forceinline__ void gemm_body(
    const float* __restrict__ A, const float* __restrict__ W,
    const float* __restrict__ bias, float* __restrict__ C,
    __half* __restrict__ VT, int N, int K)
{
    extern __shared__ float dsm[];

    const int tid = threadIdx.x;
    const int m0 = blockIdx.y * 128;
    const int n0 = blockIdx.x * 128;
    const int warp = tid >> 5;
    const int lane = tid & 31;
    const int g = lane >> 2;
    const int t = lane & 3;
    const int warpm = warp >> 2;  // 0..1
    const int warpn = warp & 3;   // 0..3

    const int laneA = (lane & 15) * 36 + ((lane >> 4) << 2);
    const int laneB = (((lane >> 4) << 3) + (lane & 7)) * 36 + (((lane >> 3) & 1) << 2);

    float acc[4][4][4];
    #pragma unroll
    for (int i = 0; i < 4; i++)
        #pragma unroll
        for (int j = 0; j < 4; j++)
            #pragma unroll
            for (int r = 0; r < 4; r++) acc[i][j][r] = 0.f;

    auto load_stage = [&](int st, int k0) {
        float* as = dsm + st * GST;
        float* bs = as + 128*36;
        #pragma unroll
        for (int i = 0; i < 4; i++) {
            int c = tid + i * 256;
            int row = c >> 3, seg = c & 7;
            cpa16(&as[row*36 + seg*4], &A[(size_t)(m0 + row) * K + k0 + seg*4]);
        }
        #pragma unroll
        for (int i = 0; i < 4; i++) {
            int c = tid + i * 256;
            int row = c >> 3, seg = c & 7;
            cpa16(&bs[row*36 + seg*4], &W[(size_t)(n0 + row) * K + k0 + seg*4]);
        }
    };

    const int iters = K / 32;            // 24
    load_stage(0, 0);  CP_COMMIT();
    load_stage(1, 32); CP_COMMIT();

    uint32_t af[2][4][4];
    uint32_t bf[2][2][4];

    for (int it = 0; it < iters; ++it) {
        CP_WAIT1();
        __syncthreads();
        if (it + 2 < iters) load_stage((it + 2) % 3, (it + 2) * 32);
        CP_COMMIT();

        const float* as = dsm + (it % 3) * GST;
        const float* bs = as + 128*36;

        #pragma unroll
        for (int ms = 0; ms < 4; ms++)
            ldsm_x4(af[0][ms][0], af[0][ms][1], af[0][ms][2], af[0][ms][3],
                    as + (warpm*64 + ms*16)*36 + laneA);
        #pragma unroll
        for (int pr = 0; pr < 2; pr++)
            ldsm_x4(bf[0][pr][0], bf[0][pr][1], bf[0][pr][2], bf[0][pr][3],
                    bs + (warpn*32 + pr*16)*36 + laneB);

        #pragma unroll
        for (int ks = 0; ks < 4; ks++) {
            int cur = ks & 1, nxt = cur ^ 1;
            if (ks + 1 < 4) {
                int k = (ks + 1) * 8;
                #pragma unroll
                for (int ms = 0; ms < 4; ms++)
                    ldsm_x4(af[nxt][ms][0], af[nxt][ms][1], af[nxt][ms][2],
                            af[nxt][ms][3],
                            as + (warpm*64 + ms*16)*36 + k + laneA);
                #pragma unroll
                for (int pr = 0; pr < 2; pr++)
                    ldsm_x4(bf[nxt][pr][0], bf[nxt][pr][1], bf[nxt][pr][2],
                            bf[nxt][pr][3],
                            bs + (warpn*32 + pr*16)*36 + k + laneB);
            }
            #pragma unroll
            for (int pr = 0; pr < 2; pr++) {
                #pragma unroll
                for (int ms = 0; ms < 4; ms++) {
                    mma_tf32(acc[ms][2*pr],   af[cur][ms][0], af[cur][ms][1],
                             af[cur][ms][2], af[cur][ms][3],
                             bf[cur][pr][0], bf[cur][pr][1]);
                    mma_tf32(acc[ms][2*pr+1], af[cur][ms][0], af[cur][ms][1],
                             af[cur][ms][2], af[cur][ms][3],
                             bf[cur][pr][2], bf[cur][pr][3]);
                }
            }
        }
    }

    #pragma unroll
    for (int ms = 0; ms < 4; ms++) {
        int row0 = m0 + warpm*64 + ms*16 + g;
        int row1 = row0 + 8;
        if (MODE == 2) {
            int b0_ = row0 / SS, s0_ = row0 - b0_*SS;
            int b1_ = row1 / SS, s1_ = row1 - b1_*SS;
            #pragma unroll
            for (int ns = 0; ns < 4; ns++) {
                int col = n0 + warpn*32 + ns*8 + 2*t;
                int h_ = col >> 6, d_ = col & 63;
                float b0v = bias[col], b1v = bias[col + 1];
                size_t base0 = ((size_t)(b0_*HH + h_)*HDD + d_) * SS;
                VT[base0 + s0_]      = __float2half(acc[ms][ns][0] + b0v);
                VT[base0 + SS + s0_] = __float2half(acc[ms][ns][1] + b1v);
                size_t base1 = ((size_t)(b1_*HH + h_)*HDD + d_) * SS;
                VT[base1 + s1_]      = __float2half(acc[ms][ns][2] + b0v);
                VT[base1 + SS + s1_] = __float2half(acc[ms][ns][3] + b1v);
            }
        } else {
            #pragma unroll
            for (int ns = 0; ns < 4; ns++) {
                int col = n0 + warpn*32 + ns*8 + 2*t;
                float b0v = bias[col], b1v = bias[col + 1];
                float2 v0, v1;
                if (MODE == 1) {
                    v0 = {rna_tf32(acc[ms][ns][0] + b0v), rna_tf32(acc[ms][ns][1] + b1v)};
                    v1 = {rna_tf32(acc[ms][ns][2] + b0v), rna_tf32(acc[ms][ns][3] + b1v)};
                } else {
                    v0 = {acc[ms][ns][0] + b0v, acc[ms][ns][1] + b1v};
                    v1 = {acc[ms][ns][2] + b0v, acc[ms][ns][3] + b1v};
                }
                *(float2*)&C[(size_t)row0 * N + col] = v0;
                *(float2*)&C[(size_t)row1 * N + col] = v1;
            }
        }
    }
}

__global__ __launch_bounds__(256, 2) void gemm_qkv(
    const float* __restrict__ A,
    const float* __restrict__ Wq, const float* __restrict__ Wk,
    const float* __restrict__ Wv,
    const float* __restrict__ bq, const float* __restrict__ bk,
    const float* __restrict__ bv,
    float* __restrict__ Cq, float* __restrict__ Ck, __half* __restrict__ Vt)
{
    int z = blockIdx.z;
    if (z == 0)      gemm_body<1>(A, Wq, bq, Cq, nullptr, DD, DD);
    else if (z == 1) gemm_body<1>(A, Wk, bk, Ck, nullptr, DD, DD);
    else             gemm_body<2>(A, Wv, bv, nullptr, Vt, DD, DD);
}

__global__ __launch_bounds__(256, 2) void gemm_single(
    const float* __restrict__ A, const float* __restrict__ W,
    const float* __restrict__ bias, float* __restrict__ C)
{
    gemm_body<0>(A, W, bias, C, nullptr, DD, DD);
}

// ---------------------------------------------------------------------------
// Fused attention per (b, h, 32-query tile).
// scores: tf32 mma (unchanged).  softmax: fp32 in regs; attn stored fp32
// (streaming); probs stored fp16 IN-PLACE over each row's own strip slot.
// AV: f16 m16n8k16 mma: warp=(m16,n32,k16), probs+V fp16 via ldmatrix;
//     V arrives pre-transposed fp16 ([dim][token]) from the V projection.
// smem unchanged: qs + kv[3] + strip = 110592 B -> 2 CTA/SM.
// ---------------------------------------------------------------------------
#define SCQ 68
#define SCK 68
#define KVPITCH (32*72)       // float pitch of a kv stage buffer
#define SCS 580
#define STRH (2*SCS)          // fp16 prob strip row stride in halfs (same slot)
#define STRV 40               // vT smem row stride (halfs)
#define QROWS 32
#define NSTAGE (SS/32)  // 18
#define RST 72
#define ATTN_SMEM_FLOATS (QROWS*SCQ + 3*KVPITCH + QROWS*SCS)  // 27648

__global__ __launch_bounds__(256, 2) void attn_fused(
    const float* __restrict__ Q, const float* __restrict__ K,
    const __half* __restrict__ Vt, float* __restrict__ attn,
    float* __restrict__ ctx)
{
    extern __shared__ float smem[];
    float* qs = smem;                         // [32][SCQ]
    float* kv = smem + QROWS*SCQ;             // 3 stage buffers
    float* sc = smem + QROWS*SCQ + 3*KVPITCH; // [32][SCS]; probs fp16 in-place

    const int qt = blockIdx.x, h = blockIdx.y, b = blockIdx.z;
    const int s0 = qt * QROWS;
    const int tid = threadIdx.x;
    const int warp = tid >> 5;
    const int lane = tid & 31;
    const int g = lane >> 2, t = lane & 3;

    const size_t qkbase = (size_t)b * SS * DD + h * HDD;
    const size_t vtbase = (size_t)(b*HH + h) * HDD * SS;

    auto load_q = [&]() {
        #pragma unroll
        for (int i = 0; i < 2; i++) {
            int c = tid + i * 256;
            int qi = c >> 4, seg = c & 15;
            cpa16(&qs[qi*SCQ + seg*4],
                  &Q[qkbase + (size_t)(s0 + qi)*DD + seg*4]);
        }
    };
    auto load_k = [&](int st, int kt) {
        float* dst = kv + st * KVPITCH;
        #pragma unroll
        for (int i = 0; i < 2; i++) {
            int c = tid + i * 256;
            int row = c >> 4, seg = c & 15;
            cpa16(&dst[row*SCK + seg*4],
                  &K[qkbase + (size_t)(kt*32 + row)*DD + seg*4]);
        }
    };
    auto load_vt = [&](int st, int kt) {     // 64 dims x 32 tokens, fp16
        __half* dst = (__half*)(kv + st * KVPITCH);
        int dim = tid >> 2, seg = tid & 3;
        cpa16(&dst[dim*STRV + seg*8],
              &Vt[vtbase + (size_t)dim*SS + kt*32 + seg*8]);
    };

    load_q();     CP_COMMIT();
    load_k(0, 0); CP_COMMIT();
    load_k(1, 1); CP_COMMIT();

    CP_WAIT2();
    __syncthreads();
    const int warpm = warp >> 2;   // scores: 0..1
    const int warpn = warp & 3;    // scores: 0..3
    uint32_t qa[8][4];
    #pragma unroll
    for (int kk = 0; kk < 8; kk++) {
        const float* pa = qs + (warpm*16 + g)*SCQ + kk*8 + t;
        qa[kk][0] = __float_as_uint(pa[0]);
        qa[kk][1] = __float_as_uint(pa[8*SCQ]);
        qa[kk][2] = __float_as_uint(pa[4]);
        qa[kk][3] = __float_as_uint(pa[8*SCQ + 4]);
    }

    const int laneKB = (lane & 7) * SCK + ((lane >> 3) << 2);
    const int laneAH = (lane & 15) * STRH + ((lane >> 4) << 3);   // prob frags
    const int laneBH = (lane & 15) * STRV + ((lane >> 4) << 3);   // V frags

    // ---- scores: QK^T into sc strip (fp32), 18 pipelined stages ----
    for (int kt = 0; kt < NSTAGE; kt++) {
        CP_WAIT1();
        __syncthreads();
        if (kt + 2 < NSTAGE) load_k((kt + 2) % 3, kt + 2);
        CP_COMMIT();

        const float* ks = kv + (kt % 3) * KVPITCH;
        float acc[4] = {0.f, 0.f, 0.f, 0.f};
        #pragma unroll
        for (int kk2 = 0; kk2 < 4; kk2++) {
            uint32_t b0, b1, b2, b3;
            ldsm_x4(b0, b1, b2, b3,
                    ks + warpn*8*SCK + kk2*16 + laneKB);
            mma_tf32(acc, qa[2*kk2][0], qa[2*kk2][1], qa[2*kk2][2],
                     qa[2*kk2][3], b0, b1);
            mma_tf32(acc, qa[2*kk2+1][0], qa[2*kk2+1][1], qa[2*kk2+1][2],
                     qa[2*kk2+1][3], b2, b3);
        }

        int row = warpm*16 + g;
        int col = kt*32 + warpn*8 + 2*t;
        float2 v0 = {acc[0]*SCALE, acc[1]*SCALE};
        *(float2*)&sc[row*SCS + col] = v0;
        float2 v1 = {acc[2]*SCALE, acc[3]*SCALE};
        *(float2*)&sc[(row+8)*SCS + col] = v1;
    }
    __syncthreads();

    // prefetch V stages 0,1 -> overlaps softmax
    load_vt(0, 0); CP_COMMIT();
    load_vt(1, 1); CP_COMMIT();

    // ---- softmax: 8 warps x 4 rows, register-resident.
    // attn: fp32 streaming store.  probs: fp16 in-place over own row slot. ----
    __half* ph = (__half*)sc;
    #pragma unroll
    for (int rr = 0; rr < 4; rr++) {
        const int r = warp*4 + rr;
        float ev[18];
        #pragma unroll
        for (int jj = 0; jj < 18; jj++) ev[jj] = sc[r*SCS + lane + 32*jj];
        float mx = ev[0];
        #pragma unroll
        for (int jj = 1; jj < 18; jj++) mx = fmaxf(mx, ev[jj]);
        #pragma unroll
        for (int o = 16; o; o >>= 1) mx = fmaxf(mx, __shfl_xor_sync(0xffffffffu, mx, o));
        float sum = 0.f;
        #pragma unroll
        for (int jj = 0; jj < 18; jj++) {
            ev[jj] = __expf(ev[jj] - mx);
            sum += ev[jj];
        }
        #pragma unroll
        for (int o = 16; o; o >>= 1) sum += __shfl_xor_sync(0xffffffffu, sum, o);
        float inv = 1.f / sum;
        float* dst = attn + (((size_t)b*HH + h)*SS + s0 + r) * (size_t)SS;
        #pragma unroll
        for (int jj = 0; jj < 18; jj++) {
            float p = ev[jj] * inv;
            __stcs(dst + lane + 32*jj, p);
            ph[r*STRH + lane + 32*jj] = __float2half(p);
        }
    }
    __syncthreads();

    // ---- AV: f16 m16n8k16. warp = (wm: m16, wn: n32, wk: k16-chunk) ----
    const int wm = warp & 1;
    const int wnn = (warp >> 1) & 1;
    const int wkk = (warp >> 2) & 1;

    float acc[4][4];   // 4 n8-tiles
    #pragma unroll
    for (int j = 0; j < 4; j++)
        #pragma unroll
        for (int r = 0; r < 4; r++) acc[j][r] = 0.f;

    for (int kt = 0; kt < NSTAGE; kt++) {
        CP_WAIT1();
        __syncthreads();
        if (kt + 2 < NSTAGE) load_vt((kt + 2) % 3, kt + 2);
        CP_COMMIT();

        const __half* vh = (const __half*)(kv + (kt % 3) * KVPITCH);

        uint32_t a0, a1, a2, a3;
        ldsm_x4(a0, a1, a2, a3,
                ph + wm*16*STRH + kt*32 + wkk*16 + laneAH);
        #pragma unroll
        for (int nblk = 0; nblk < 2; nblk++) {
            uint32_t b0, b1, b2, b3;   // m0,m1,m2,m3
            ldsm_x4(b0, b1, b2, b3,
                    vh + (wnn*32 + nblk*16)*STRV + wkk*16 + laneBH);
            mma_f16(acc[nblk*2 + 0], a0, a1, a2, a3, b0, b2);
            mma_f16(acc[nblk*2 + 1], a0, a1, a2, a3, b1, b3);
        }
    }

    // ---- reduce 2 k-partials through smem (strip region reused) ----
    __syncthreads();
    float* red = sc;   // [2][32][RST]
    #pragma unroll
    for (int nt = 0; nt < 4; nt++) {
        int col = wnn*32 + nt*8 + 2*t;
        float2 v0 = {acc[nt][0], acc[nt][1]};
        *(float2*)&red[wkk*32*RST + (wm*16 + g)*RST + col] = v0;
        float2 v1 = {acc[nt][2], acc[nt][3]};
        *(float2*)&red[wkk*32*RST + (wm*16 + g + 8)*RST + col] = v1;
    }
    __syncthreads();

    #pragma unroll
    for (int i = 0; i < 2; i++) {
        int f4 = tid + i*256;
        int row = f4 >> 4, c4 = f4 & 15;
        const float* p0 = red + row*RST + c4*4;
        float4 s0v = *(const float4*)(p0);
        float4 s1v = *(const float4*)(p0 + 32*RST);
        float4 o;
        o.x = rna_tf32(s0v.x + s1v.x);
        o.y = rna_tf32(s0v.y + s1v.y);
        o.z = rna_tf32(s0v.z + s1v.z);
        o.w = rna_tf32(s0v.w + s1v.w);
        *(float4*)&ctx[((size_t)(b*SS + s0 + row))*DD + h*HDD + c4*4] = o;
    }
}

// ===========================================================================
extern "C" void kernel_launch(void* const* d_in, const int* in_sizes, int n_in,
                              void* d_out, int out_size)
{
    const float* x  = (const float*)d_in[0];
    const float* Wq = (const float*)d_in[1];
    const float* bq = (const float*)d_in[2];
    const float* Wk = (const float*)d_in[3];
    const float* bk = (const float*)d_in[4];
    const float* Wv = (const float*)d_in[5];
    const float* bv = (const float*)d_in[6];
    const float* Wo = (const float*)d_in[7];
    const float* bo = (const float*)d_in[8];

    float* out = (float*)d_out;
    float* attn;
    if (out_size >= OUT_ELEMS + ATTN_ELEMS) {
        attn = out + OUT_ELEMS;
    } else {
        void* p; cudaGetSymbolAddress(&p, g_attn_fallback);
        attn = (float*)p;
    }

    float *q, *k, *ctx, *xr, *wq, *wk, *wv, *wo;
    __half* vt;
    { void* p; cudaGetSymbolAddress(&p, g_q);   q   = (float*)p; }
    { void* p; cudaGetSymbolAddress(&p, g_k);   k   = (float*)p; }
    { void* p; cudaGetSymbolAddress(&p, g_vt);  vt  = (__half*)p; }
    { void* p; cudaGetSymbolAddress(&p, g_ctx); ctx = (float*)p; }
    { void* p; cudaGetSymbolAddress(&p, g_xr);  xr  = (float*)p; }
    { void* p; cudaGetSymbolAddress(&p, g_wq);  wq  = (float*)p; }
    { void* p; cudaGetSymbolAddress(&p, g_wk);  wk  = (float*)p; }
    { void* p; cudaGetSymbolAddress(&p, g_wv);  wv  = (float*)p; }
    { void* p; cudaGetSymbolAddress(&p, g_wo);  wo  = (float*)p; }

    const int gemm_smem = 3 * GST * (int)sizeof(float);          // 110592
    cudaFuncSetAttribute(gemm_qkv,
                         cudaFuncAttributeMaxDynamicSharedMemorySize, gemm_smem);
    cudaFuncSetAttribute(gemm_single,
                         cudaFuncAttributeMaxDynamicSharedMemorySize, gemm_smem);
    const int attn_smem = ATTN_SMEM_FLOATS * (int)sizeof(float); // 110592
    cudaFuncSetAttribute(attn_fused,
                         cudaFuncAttributeMaxDynamicSharedMemorySize, attn_smem);

    // 1) tf32 pre-rounding (x and all four W)
    round_tf32_kernel<<<1184, 256>>>(x, xr, OUT_ELEMS/4);
    dim3 gW(288, 4);
    round_w4_kernel<<<gW, 256>>>(Wq, Wk, Wv, Wo, wq, wk, wv, wo, (DD*DD)/4);

    // 2) fused Q/K/V projections (Q,K rna fp32; V fp16 transposed)
    dim3 gQKV(DD/128, MTOK/128, 3);
    gemm_qkv<<<gQKV, 256, gemm_smem>>>(xr, wq, wk, wv, bq, bk, bv, q, k, vt);

    // 3) fused scores + softmax + AV
    dim3 gAttn(SS/QROWS, HH, BB);         // (18, 12, 32)
    attn_fused<<<gAttn, 256, attn_smem>>>(q, k, vt, attn, ctx);

    // 4) output projection
    dim3 gO(DD/128, MTOK/128);
    gemm_single<<<gO, 256, gemm_smem>>>(ctx, wo, bo, out);
}

// round 15
// speedup vs baseline: 1.1175x; 1.1175x over previous
#include <cuda_runtime.h>
#include <cuda_fp16.h>
#include <cstdint>
#include <cstddef>

#define BB 32
#define SS 576
#define DD 768
#define HH 12
#define HDD 64
#define MTOK (BB*SS)               // 18432
#define OUT_ELEMS (BB*SS*DD)       // 14155776
#define ATTN_ELEMS (BB*HH*SS*SS)   // 127401984
#define SCALE 0.125f

// ---- scratch (static device globals; no runtime allocation) ----
__device__ float g_q[OUT_ELEMS];
__device__ float g_k[OUT_ELEMS];
__device__ __half g_vt[OUT_ELEMS];   // V fp16, transposed: [b][h][dim][token]
__device__ float g_ctx[OUT_ELEMS];
__device__ float g_xr[OUT_ELEMS];
__device__ float g_wq[DD*DD], g_wk[DD*DD], g_wv[DD*DD], g_wo[DD*DD];
__device__ float g_attn_fallback[ATTN_ELEMS];

// ---------------------------------------------------------------------------
__device__ __forceinline__ float rna_tf32(float x) {
    unsigned u;
    asm("cvt.rna.tf32.f32 %0, %1;" : "=r"(u) : "f"(x));
    return __uint_as_float(u);
}

__device__ __forceinline__ void mma_tf32(float c[4],
    uint32_t a0, uint32_t a1, uint32_t a2, uint32_t a3,
    uint32_t b0, uint32_t b1)
{
    asm volatile(
        "mma.sync.aligned.m16n8k8.row.col.f32.tf32.tf32.f32 "
        "{%0,%1,%2,%3}, {%4,%5,%6,%7}, {%8,%9}, {%0,%1,%2,%3};"
        : "+f"(c[0]), "+f"(c[1]), "+f"(c[2]), "+f"(c[3])
        : "r"(a0), "r"(a1), "r"(a2), "r"(a3), "r"(b0), "r"(b1));
}

__device__ __forceinline__ void mma_f16(float c[4],
    uint32_t a0, uint32_t a1, uint32_t a2, uint32_t a3,
    uint32_t b0, uint32_t b1)
{
    asm volatile(
        "mma.sync.aligned.m16n8k16.row.col.f32.f16.f16.f32 "
        "{%0,%1,%2,%3}, {%4,%5,%6,%7}, {%8,%9}, {%0,%1,%2,%3};"
        : "+f"(c[0]), "+f"(c[1]), "+f"(c[2]), "+f"(c[3])
        : "r"(a0), "r"(a1), "r"(a2), "r"(a3), "r"(b0), "r"(b1));
}

__device__ __forceinline__ void ldsm_x4(uint32_t& r0, uint32_t& r1,
                                        uint32_t& r2, uint32_t& r3,
                                        const void* p)
{
    uint32_t a = (uint32_t)__cvta_generic_to_shared(p);
    asm volatile("ldmatrix.sync.aligned.m8n8.x4.shared.b16 {%0,%1,%2,%3}, [%4];"
                 : "=r"(r0), "=r"(r1), "=r"(r2), "=r"(r3) : "r"(a));
}

__device__ __forceinline__ void cpa16(void* dst, const void* src) {
    uint32_t d = (uint32_t)__cvta_generic_to_shared(dst);
    asm volatile("cp.async.cg.shared.global [%0], [%1], 16;\n"
                 :: "r"(d), "l"(src));
}
#define CP_COMMIT() asm volatile("cp.async.commit_group;\n" ::)
#define CP_WAIT1()  asm volatile("cp.async.wait_group 1;\n" ::)
#define CP_WAIT2()  asm volatile("cp.async.wait_group 2;\n" ::)

// ---------------------------------------------------------------------------
__global__ void round_tf32_kernel(const float* __restrict__ in,
                                  float* __restrict__ out, int n4)
{
    for (int i = blockIdx.x * blockDim.x + threadIdx.x; i < n4;
         i += gridDim.x * blockDim.x) {
        float4 v = ((const float4*)in)[i];
        v.x = rna_tf32(v.x); v.y = rna_tf32(v.y);
        v.z = rna_tf32(v.z); v.w = rna_tf32(v.w);
        ((float4*)out)[i] = v;
    }
}

__global__ void round_w4_kernel(
    const float* __restrict__ w0, const float* __restrict__ w1,
    const float* __restrict__ w2, const float* __restrict__ w3,
    float* __restrict__ o0, float* __restrict__ o1,
    float* __restrict__ o2, float* __restrict__ o3, int n4)
{
    int z = blockIdx.y;
    const float* in = (z == 0) ? w0 : (z == 1) ? w1 : (z == 2) ? w2 : w3;
    float* out      = (z == 0) ? o0 : (z == 1) ? o1 : (z == 2) ? o2 : o3;
    for (int i = blockIdx.x * blockDim.x + threadIdx.x; i < n4;
         i += gridDim.x * blockDim.x) {
        float4 v = ((const float4*)in)[i];
        v.x = rna_tf32(v.x); v.y = rna_tf32(v.y);
        v.z = rna_tf32(v.z); v.w = rna_tf32(v.w);
        ((float4*)out)[i] = v;
    }
}

// ---------------------------------------------------------------------------
// GEMM: C[M,N] = A[M,K] @ W^T + bias.  A,W pre-rounded to tf32.
// MODE 0: plain fp32 store.  MODE 1: rna-rounded fp32 store (Q,K).
// MODE 2: fp16 transposed store into VT[b][h][dim][token] (V).
// BM=128, BN=128, BK=32, 256 threads, ldmatrix frags (double-buffered),
// 3-stage cp.async pipeline, one __syncthreads per iteration.
// ---------------------------------------------------------------------------
#define GST (2*128*36)   // floats per stage (A+B)

template <int MODE>
__device__ __forceinline__ void gemm_body(
    const float* __restrict__ A, const float* __restrict__ W,
    const float* __restrict__ bias, float* __restrict__ C,
    __half* __restrict__ VT, int N, int K)
{
    extern __shared__ float dsm[];

    const int tid = threadIdx.x;
    const int m0 = blockIdx.y * 128;
    const int n0 = blockIdx.x * 128;
    const int warp = tid >> 5;
    const int lane = tid & 31;
    const int g = lane >> 2;
    const int t = lane & 3;
    const int warpm = warp >> 2;  // 0..1
    const int warpn = warp & 3;   // 0..3

    const int laneA = (lane & 15) * 36 + ((lane >> 4) << 2);
    const int laneB = (((lane >> 4) << 3) + (lane & 7)) * 36 + (((lane >> 3) & 1) << 2);

    float acc[4][4][4];
    #pragma unroll
    for (int i = 0; i < 4; i++)
        #pragma unroll
        for (int j = 0; j < 4; j++)
            #pragma unroll
            for (int r = 0; r < 4; r++) acc[i][j][r] = 0.f;

    auto load_stage = [&](int st, int k0) {
        float* as = dsm + st * GST;
        float* bs = as + 128*36;
        #pragma unroll
        for (int i = 0; i < 4; i++) {
            int c = tid + i * 256;
            int row = c >> 3, seg = c & 7;
            cpa16(&as[row*36 + seg*4], &A[(size_t)(m0 + row) * K + k0 + seg*4]);
        }
        #pragma unroll
        for (int i = 0; i < 4; i++) {
            int c = tid + i * 256;
            int row = c >> 3, seg = c & 7;
            cpa16(&bs[row*36 + seg*4], &W[(size_t)(n0 + row) * K + k0 + seg*4]);
        }
    };

    const int iters = K / 32;            // 24
    load_stage(0, 0);  CP_COMMIT();
    load_stage(1, 32); CP_COMMIT();

    uint32_t af[2][4][4];
    uint32_t bf[2][2][4];

    for (int it = 0; it < iters; ++it) {
        CP_WAIT1();
        __syncthreads();
        if (it + 2 < iters) load_stage((it + 2) % 3, (it + 2) * 32);
        CP_COMMIT();

        const float* as = dsm + (it % 3) * GST;
        const float* bs = as + 128*36;

        #pragma unroll
        for (int ms = 0; ms < 4; ms++)
            ldsm_x4(af[0][ms][0], af[0][ms][1], af[0][ms][2], af[0][ms][3],
                    as + (warpm*64 + ms*16)*36 + laneA);
        #pragma unroll
        for (int pr = 0; pr < 2; pr++)
            ldsm_x4(bf[0][pr][0], bf[0][pr][1], bf[0][pr][2], bf[0][pr][3],
                    bs + (warpn*32 + pr*16)*36 + laneB);

        #pragma unroll
        for (int ks = 0; ks < 4; ks++) {
            int cur = ks & 1, nxt = cur ^ 1;
            if (ks + 1 < 4) {
                int k = (ks + 1) * 8;
                #pragma unroll
                for (int ms = 0; ms < 4; ms++)
                    ldsm_x4(af[nxt][ms][0], af[nxt][ms][1], af[nxt][ms][2],
                            af[nxt][ms][3],
                            as + (warpm*64 + ms*16)*36 + k + laneA);
                #pragma unroll
                for (int pr = 0; pr < 2; pr++)
                    ldsm_x4(bf[nxt][pr][0], bf[nxt][pr][1], bf[nxt][pr][2],
                            bf[nxt][pr][3],
                            bs + (warpn*32 + pr*16)*36 + k + laneB);
            }
            #pragma unroll
            for (int pr = 0; pr < 2; pr++) {
                #pragma unroll
                for (int ms = 0; ms < 4; ms++) {
                    mma_tf32(acc[ms][2*pr],   af[cur][ms][0], af[cur][ms][1],
                             af[cur][ms][2], af[cur][ms][3],
                             bf[cur][pr][0], bf[cur][pr][1]);
                    mma_tf32(acc[ms][2*pr+1], af[cur][ms][0], af[cur][ms][1],
                             af[cur][ms][2], af[cur][ms][3],
                             bf[cur][pr][2], bf[cur][pr][3]);
                }
            }
        }
    }

    #pragma unroll
    for (int ms = 0; ms < 4; ms++) {
        int row0 = m0 + warpm*64 + ms*16 + g;
        int row1 = row0 + 8;
        if (MODE == 2) {
            int b0_ = row0 / SS, s0_ = row0 - b0_*SS;
            int b1_ = row1 / SS, s1_ = row1 - b1_*SS;
            #pragma unroll
            for (int ns = 0; ns < 4; ns++) {
                int col = n0 + warpn*32 + ns*8 + 2*t;
                int h_ = col >> 6, d_ = col & 63;
                float b0v = bias[col], b1v = bias[col + 1];
                size_t base0 = ((size_t)(b0_*HH + h_)*HDD + d_) * SS;
                VT[base0 + s0_]      = __float2half(acc[ms][ns][0] + b0v);
                VT[base0 + SS + s0_] = __float2half(acc[ms][ns][1] + b1v);
                size_t base1 = ((size_t)(b1_*HH + h_)*HDD + d_) * SS;
                VT[base1 + s1_]      = __float2half(acc[ms][ns][2] + b0v);
                VT[base1 + SS + s1_] = __float2half(acc[ms][ns][3] + b1v);
            }
        } else {
            #pragma unroll
            for (int ns = 0; ns < 4; ns++) {
                int col = n0 + warpn*32 + ns*8 + 2*t;
                float b0v = bias[col], b1v = bias[col + 1];
                float2 v0, v1;
                if (MODE == 1) {
                    v0 = {rna_tf32(acc[ms][ns][0] + b0v), rna_tf32(acc[ms][ns][1] + b1v)};
                    v1 = {rna_tf32(acc[ms][ns][2] + b0v), rna_tf32(acc[ms][ns][3] + b1v)};
                } else {
                    v0 = {acc[ms][ns][0] + b0v, acc[ms][ns][1] + b1v};
                    v1 = {acc[ms][ns][2] + b0v, acc[ms][ns][3] + b1v};
                }
                *(float2*)&C[(size_t)row0 * N + col] = v0;
                *(float2*)&C[(size_t)row1 * N + col] = v1;
            }
        }
    }
}

__global__ __launch_bounds__(256, 2) void gemm_qkv(
    const float* __restrict__ A,
    const float* __restrict__ Wq, const float* __restrict__ Wk,
    const float* __restrict__ Wv,
    const float* __restrict__ bq, const float* __restrict__ bk,
    const float* __restrict__ bv,
    float* __restrict__ Cq, float* __restrict__ Ck, __half* __restrict__ Vt)
{
    int z = blockIdx.z;
    if (z == 0)      gemm_body<1>(A, Wq, bq, Cq, nullptr, DD, DD);
    else if (z == 1) gemm_body<1>(A, Wk, bk, Ck, nullptr, DD, DD);
    else             gemm_body<2>(A, Wv, bv, nullptr, Vt, DD, DD);
}

__global__ __launch_bounds__(256, 2) void gemm_single(
    const float* __restrict__ A, const float* __restrict__ W,
    const float* __restrict__ bias, float* __restrict__ C)
{
    gemm_body<0>(A, W, bias, C, nullptr, DD, DD);
}

// ---------------------------------------------------------------------------
// Fused attention per (b, h, 32-query tile).
// Score strip stored FP16 -> smem 73728 B -> 3 CTAs/SM (the latency lever).
// scores: tf32 mma, epilogue converts to fp16 strip.
// softmax: fp32 in regs from fp16 strip; attn fp32 streaming store; probs fp16
// in place.  AV: f16 m16n8k16 (R14-verified mapping), V fp16 pre-transposed.
// ---------------------------------------------------------------------------
#define SCQ 68
#define SCK 68
#define KVPITCH (32*72)       // float pitch of a kv stage buffer
#define SCH 584               // fp16 strip row stride (halfs); 584*2B = 292 words == 4 mod 32
#define STRV 40               // vT smem row stride (halfs)
#define QROWS 32
#define NSTAGE (SS/32)  // 18
#define RST 72
#define ATTN_SMEM_BYTES ((QROWS*SCQ + 3*KVPITCH)*4 + QROWS*SCH*2)  // 73728

__global__ __launch_bounds__(256, 3) void attn_fused(
    const float* __restrict__ Q, const float* __restrict__ K,
    const __half* __restrict__ Vt, float* __restrict__ attn,
    float* __restrict__ ctx)
{
    extern __shared__ float smem[];
    float* qs = smem;                             // [32][SCQ] fp32
    float* kv = smem + QROWS*SCQ;                 // 3 stage buffers fp32
    __half* ph = (__half*)(smem + QROWS*SCQ + 3*KVPITCH);  // [32][SCH] fp16

    const int qt = blockIdx.x, h = blockIdx.y, b = blockIdx.z;
    const int s0 = qt * QROWS;
    const int tid = threadIdx.x;
    const int warp = tid >> 5;
    const int lane = tid & 31;
    const int g = lane >> 2, t = lane & 3;

    const size_t qkbase = (size_t)b * SS * DD + h * HDD;
    const size_t vtbase = (size_t)(b*HH + h) * HDD * SS;

    auto load_q = [&]() {
        #pragma unroll
        for (int i = 0; i < 2; i++) {
            int c = tid + i * 256;
            int qi = c >> 4, seg = c & 15;
            cpa16(&qs[qi*SCQ + seg*4],
                  &Q[qkbase + (size_t)(s0 + qi)*DD + seg*4]);
        }
    };
    auto load_k = [&](int st, int kt) {
        float* dst = kv + st * KVPITCH;
        #pragma unroll
        for (int i = 0; i < 2; i++) {
            int c = tid + i * 256;
            int row = c >> 4, seg = c & 15;
            cpa16(&dst[row*SCK + seg*4],
                  &K[qkbase + (size_t)(kt*32 + row)*DD + seg*4]);
        }
    };
    auto load_vt = [&](int st, int kt) {     // 64 dims x 32 tokens, fp16
        __half* dst = (__half*)(kv + st * KVPITCH);
        int dim = tid >> 2, seg = tid & 3;
        cpa16(&dst[dim*STRV + seg*8],
              &Vt[vtbase + (size_t)dim*SS + kt*32 + seg*8]);
    };

    load_q();     CP_COMMIT();
    load_k(0, 0); CP_COMMIT();
    load_k(1, 1); CP_COMMIT();

    CP_WAIT2();
    __syncthreads();
    const int warpm = warp >> 2;   // scores: 0..1
    const int warpn = warp & 3;    // scores: 0..3
    uint32_t qa[8][4];
    #pragma unroll
    for (int kk = 0; kk < 8; kk++) {
        const float* pa = qs + (warpm*16 + g)*SCQ + kk*8 + t;
        qa[kk][0] = __float_as_uint(pa[0]);
        qa[kk][1] = __float_as_uint(pa[8*SCQ]);
        qa[kk][2] = __float_as_uint(pa[4]);
        qa[kk][3] = __float_as_uint(pa[8*SCQ + 4]);
    }

    const int laneKB = (lane & 7) * SCK + ((lane >> 3) << 2);
    const int laneAH = (lane & 15) * SCH + ((lane >> 4) << 3);   // prob frags
    const int laneBH = (lane & 15) * STRV + ((lane >> 4) << 3);  // V frags

    // ---- scores: QK^T -> fp16 strip, 18 pipelined stages ----
    for (int kt = 0; kt < NSTAGE; kt++) {
        CP_WAIT1();
        __syncthreads();
        if (kt + 2 < NSTAGE) load_k((kt + 2) % 3, kt + 2);
        CP_COMMIT();

        const float* ks = kv + (kt % 3) * KVPITCH;
        float acc[4] = {0.f, 0.f, 0.f, 0.f};
        #pragma unroll
        for (int kk2 = 0; kk2 < 4; kk2++) {
            uint32_t b0, b1, b2, b3;
            ldsm_x4(b0, b1, b2, b3,
                    ks + warpn*8*SCK + kk2*16 + laneKB);
            mma_tf32(acc, qa[2*kk2][0], qa[2*kk2][1], qa[2*kk2][2],
                     qa[2*kk2][3], b0, b1);
            mma_tf32(acc, qa[2*kk2+1][0], qa[2*kk2+1][1], qa[2*kk2+1][2],
                     qa[2*kk2+1][3], b2, b3);
        }

        int row = warpm*16 + g;
        int col = kt*32 + warpn*8 + 2*t;
        *(__half2*)(ph + row*SCH + col) =
            __floats2half2_rn(acc[0]*SCALE, acc[1]*SCALE);
        *(__half2*)(ph + (row+8)*SCH + col) =
            __floats2half2_rn(acc[2]*SCALE, acc[3]*SCALE);
    }
    __syncthreads();

    // prefetch V stages 0,1 -> overlaps softmax
    load_vt(0, 0); CP_COMMIT();
    load_vt(1, 1); CP_COMMIT();

    // ---- softmax: 8 warps x 4 rows, register-resident (fp16 strip) ----
    #pragma unroll
    for (int rr = 0; rr < 4; rr++) {
        const int r = warp*4 + rr;
        float ev[18];
        #pragma unroll
        for (int jj = 0; jj < 18; jj++)
            ev[jj] = __half2float(ph[r*SCH + lane + 32*jj]);
        float mx = ev[0];
        #pragma unroll
        for (int jj = 1; jj < 18; jj++) mx = fmaxf(mx, ev[jj]);
        #pragma unroll
        for (int o = 16; o; o >>= 1) mx = fmaxf(mx, __shfl_xor_sync(0xffffffffu, mx, o));
        float sum = 0.f;
        #pragma unroll
        for (int jj = 0; jj < 18; jj++) {
            ev[jj] = __expf(ev[jj] - mx);
            sum += ev[jj];
        }
        #pragma unroll
        for (int o = 16; o; o >>= 1) sum += __shfl_xor_sync(0xffffffffu, sum, o);
        float inv = 1.f / sum;
        float* dst = attn + (((size_t)b*HH + h)*SS + s0 + r) * (size_t)SS;
        #pragma unroll
        for (int jj = 0; jj < 18; jj++) {
            float p = ev[jj] * inv;
            __stcs(dst + lane + 32*jj, p);
            ph[r*SCH + lane + 32*jj] = __float2half(p);
        }
    }
    __syncthreads();

    // ---- AV: f16 m16n8k16. warp = (wm: m16, wn: n32, wk: k16-chunk) ----
    const int wm = warp & 1;
    const int wnn = (warp >> 1) & 1;
    const int wkk = (warp >> 2) & 1;

    float acc[4][4];   // 4 n8-tiles
    #pragma unroll
    for (int j = 0; j < 4; j++)
        #pragma unroll
        for (int r = 0; r < 4; r++) acc[j][r] = 0.f;

    for (int kt = 0; kt < NSTAGE; kt++) {
        CP_WAIT1();
        __syncthreads();
        if (kt + 2 < NSTAGE) load_vt((kt + 2) % 3, kt + 2);
        CP_COMMIT();

        const __half* vh = (const __half*)(kv + (kt % 3) * KVPITCH);

        uint32_t a0, a1, a2, a3;
        ldsm_x4(a0, a1, a2, a3,
                ph + wm*16*SCH + kt*32 + wkk*16 + laneAH);
        #pragma unroll
        for (int nblk = 0; nblk < 2; nblk++) {
            uint32_t b0, b1, b2, b3;
            ldsm_x4(b0, b1, b2, b3,
                    vh + (wnn*32 + nblk*16)*STRV + wkk*16 + laneBH);
            mma_f16(acc[nblk*2 + 0], a0, a1, a2, a3, b0, b2);
            mma_f16(acc[nblk*2 + 1], a0, a1, a2, a3, b1, b3);
        }
    }

    // ---- reduce 2 k-partials through smem (strip region reused) ----
    __syncthreads();
    float* red = (float*)ph;   // [2][32][RST] fp32 (18.4 KB < 36.5 KB strip)
    #pragma unroll
    for (int nt = 0; nt < 4; nt++) {
        int col = wnn*32 + nt*8 + 2*t;
        float2 v0 = {acc[nt][0], acc[nt][1]};
        *(float2*)&red[wkk*32*RST + (wm*16 + g)*RST + col] = v0;
        float2 v1 = {acc[nt][2], acc[nt][3]};
        *(float2*)&red[wkk*32*RST + (wm*16 + g + 8)*RST + col] = v1;
    }
    __syncthreads();

    #pragma unroll
    for (int i = 0; i < 2; i++) {
        int f4 = tid + i*256;
        int row = f4 >> 4, c4 = f4 & 15;
        const float* p0 = red + row*RST + c4*4;
        float4 s0v = *(const float4*)(p0);
        float4 s1v = *(const float4*)(p0 + 32*RST);
        float4 o;
        o.x = rna_tf32(s0v.x + s1v.x);
        o.y = rna_tf32(s0v.y + s1v.y);
        o.z = rna_tf32(s0v.z + s1v.z);
        o.w = rna_tf32(s0v.w + s1v.w);
        *(float4*)&ctx[((size_t)(b*SS + s0 + row))*DD + h*HDD + c4*4] = o;
    }
}

// ===========================================================================
extern "C" void kernel_launch(void* const* d_in, const int* in_sizes, int n_in,
                              void* d_out, int out_size)
{
    const float* x  = (const float*)d_in[0];
    const float* Wq = (const float*)d_in[1];
    const float* bq = (const float*)d_in[2];
    const float* Wk = (const float*)d_in[3];
    const float* bk = (const float*)d_in[4];
    const float* Wv = (const float*)d_in[5];
    const float* bv = (const float*)d_in[6];
    const float* Wo = (const float*)d_in[7];
    const float* bo = (const float*)d_in[8];

    float* out = (float*)d_out;
    float* attn;
    if (out_size >= OUT_ELEMS + ATTN_ELEMS) {
        attn = out + OUT_ELEMS;
    } else {
        void* p; cudaGetSymbolAddress(&p, g_attn_fallback);
        attn = (float*)p;
    }

    float *q, *k, *ctx, *xr, *wq, *wk, *wv, *wo;
    __half* vt;
    { void* p; cudaGetSymbolAddress(&p, g_q);   q   = (float*)p; }
    { void* p; cudaGetSymbolAddress(&p, g_k);   k   = (float*)p; }
    { void* p; cudaGetSymbolAddress(&p, g_vt);  vt  = (__half*)p; }
    { void* p; cudaGetSymbolAddress(&p, g_ctx); ctx = (float*)p; }
    { void* p; cudaGetSymbolAddress(&p, g_xr);  xr  = (float*)p; }
    { void* p; cudaGetSymbolAddress(&p, g_wq);  wq  = (float*)p; }
    { void* p; cudaGetSymbolAddress(&p, g_wk);  wk  = (float*)p; }
    { void* p; cudaGetSymbolAddress(&p, g_wv);  wv  = (float*)p; }
    { void* p; cudaGetSymbolAddress(&p, g_wo);  wo  = (float*)p; }

    const int gemm_smem = 3 * GST * (int)sizeof(float);          // 110592
    cudaFuncSetAttribute(gemm_qkv,
                         cudaFuncAttributeMaxDynamicSharedMemorySize, gemm_smem);
    cudaFuncSetAttribute(gemm_single,
                         cudaFuncAttributeMaxDynamicSharedMemorySize, gemm_smem);
    cudaFuncSetAttribute(attn_fused,
                         cudaFuncAttributeMaxDynamicSharedMemorySize, ATTN_SMEM_BYTES);

    // 1) tf32 pre-rounding (x and all four W)
    round_tf32_kernel<<<1184, 256>>>(x, xr, OUT_ELEMS/4);
    dim3 gW(288, 4);
    round_w4_kernel<<<gW, 256>>>(Wq, Wk, Wv, Wo, wq, wk, wv, wo, (DD*DD)/4);

    // 2) fused Q/K/V projections (Q,K rna fp32; V fp16 transposed)
    dim3 gQKV(DD/128, MTOK/128, 3);
    gemm_qkv<<<gQKV, 256, gemm_smem>>>(xr, wq, wk, wv, bq, bk, bv, q, k, vt);

    // 3) fused scores + softmax + AV (3 CTAs/SM)
    dim3 gAttn(SS/QROWS, HH, BB);         // (18, 12, 32)
    attn_fused<<<gAttn, 256, ATTN_SMEM_BYTES>>>(q, k, vt, attn, ctx);

    // 4) output projection
    dim3 gO(DD/128, MTOK/128);
    gemm_single<<<gO, 256, gemm_smem>>>(ctx, wo, bo, out);
}

// round 16
// speedup vs baseline: 1.5018x; 1.3438x over previous
#include <cuda_runtime.h>
#include <cuda_fp16.h>
#include <cstdint>
#include <cstddef>

#define BB 32
#define SS 576
#define DD 768
#define HH 12
#define HDD 64
#define MTOK (BB*SS)               // 18432
#define OUT_ELEMS (BB*SS*DD)       // 14155776
#define ATTN_ELEMS (BB*HH*SS*SS)   // 127401984
#define SCALE 0.125f

// ---- scratch (static device globals; no runtime allocation) ----
__device__ __half g_xh[OUT_ELEMS];            // fp16 x
__device__ __half g_qh[OUT_ELEMS];            // fp16 Q [b][s][d]
__device__ __half g_kh[OUT_ELEMS];            // fp16 K [b][s][d]
__device__ __half g_vt[OUT_ELEMS];            // fp16 V transposed [b][h][dim][tok]
__device__ __half g_ctxh[OUT_ELEMS];          // fp16 ctx
__device__ __half g_wqh[DD*DD], g_wkh[DD*DD], g_wvh[DD*DD], g_woh[DD*DD];
__device__ float g_attn_fallback[ATTN_ELEMS];

// ---------------------------------------------------------------------------
__device__ __forceinline__ void mma_f16(float c[4],
    uint32_t a0, uint32_t a1, uint32_t a2, uint32_t a3,
    uint32_t b0, uint32_t b1)
{
    asm volatile(
        "mma.sync.aligned.m16n8k16.row.col.f32.f16.f16.f32 "
        "{%0,%1,%2,%3}, {%4,%5,%6,%7}, {%8,%9}, {%0,%1,%2,%3};"
        : "+f"(c[0]), "+f"(c[1]), "+f"(c[2]), "+f"(c[3])
        : "r"(a0), "r"(a1), "r"(a2), "r"(a3), "r"(b0), "r"(b1));
}

__device__ __forceinline__ void ldsm_x4(uint32_t& r0, uint32_t& r1,
                                        uint32_t& r2, uint32_t& r3,
                                        const void* p)
{
    uint32_t a = (uint32_t)__cvta_generic_to_shared(p);
    asm volatile("ldmatrix.sync.aligned.m8n8.x4.shared.b16 {%0,%1,%2,%3}, [%4];"
                 : "=r"(r0), "=r"(r1), "=r"(r2), "=r"(r3) : "r"(a));
}

__device__ __forceinline__ void ldsm_x2(uint32_t& r0, uint32_t& r1,
                                        const void* p)
{
    uint32_t a = (uint32_t)__cvta_generic_to_shared(p);
    asm volatile("ldmatrix.sync.aligned.m8n8.x2.shared.b16 {%0,%1}, [%2];"
                 : "=r"(r0), "=r"(r1) : "r"(a));
}

__device__ __forceinline__ void cpa16(void* dst, const void* src) {
    uint32_t d = (uint32_t)__cvta_generic_to_shared(dst);
    asm volatile("cp.async.cg.shared.global [%0], [%1], 16;\n"
                 :: "r"(d), "l"(src));
}
#define CP_COMMIT() asm volatile("cp.async.commit_group;\n" ::)
#define CP_WAIT1()  asm volatile("cp.async.wait_group 1;\n" ::)
#define CP_WAIT2()  asm volatile("cp.async.wait_group 2;\n" ::)

// ---------------------------------------------------------------------------
// fp32 -> fp16 conversion passes
__global__ void tohalf_kernel(const float* __restrict__ in,
                              __half* __restrict__ out, int n4)
{
    for (int i = blockIdx.x * blockDim.x + threadIdx.x; i < n4;
         i += gridDim.x * blockDim.x) {
        float4 v = ((const float4*)in)[i];
        *(__half2*)&out[i*4]     = __floats2half2_rn(v.x, v.y);
        *(__half2*)&out[i*4 + 2] = __floats2half2_rn(v.z, v.w);
    }
}

__global__ void tohalf_w4_kernel(
    const float* __restrict__ w0, const float* __restrict__ w1,
    const float* __restrict__ w2, const float* __restrict__ w3,
    __half* __restrict__ o0, __half* __restrict__ o1,
    __half* __restrict__ o2, __half* __restrict__ o3, int n4)
{
    int z = blockIdx.y;
    const float* in = (z == 0) ? w0 : (z == 1) ? w1 : (z == 2) ? w2 : w3;
    __half* out     = (z == 0) ? o0 : (z == 1) ? o1 : (z == 2) ? o2 : o3;
    for (int i = blockIdx.x * blockDim.x + threadIdx.x; i < n4;
         i += gridDim.x * blockDim.x) {
        float4 v = ((const float4*)in)[i];
        *(__half2*)&out[i*4]     = __floats2half2_rn(v.x, v.y);
        *(__half2*)&out[i*4 + 2] = __floats2half2_rn(v.z, v.w);
    }
}

// ---------------------------------------------------------------------------
// fp16 GEMM: C = A[M,K] @ W^T + bias.  A,W fp16; accum fp32.
// MODE 0: fp32 C.  MODE 1: fp16 row-major CH (Q,K).  MODE 2: fp16 transposed VT.
// BM=128, BN=128, BK=32 halfs, 256 threads, f16 m16n8k16,
// 3-stage cp.async pipeline, one __syncthreads per iteration.
// smem: 3 stages x 2 x 128 x 40 halfs = 61440 B.
// ---------------------------------------------------------------------------
#define GH 40                // smem row stride (halfs)
#define GSTH (2*128*GH)      // halfs per stage

template <int MODE>
__device__ __forceinline__ void gemm_f16(
    const __half* __restrict__ A, const __half* __restrict__ W,
    const float* __restrict__ bias, float* __restrict__ C,
    __half* __restrict__ CH, int N, int K)
{
    extern __shared__ __align__(16) char dsmraw[];
    __half* dsm = (__half*)dsmraw;

    const int tid = threadIdx.x;
    const int m0 = blockIdx.y * 128;
    const int n0 = blockIdx.x * 128;
    const int warp = tid >> 5;
    const int lane = tid & 31;
    const int g = lane >> 2;
    const int t = lane & 3;
    const int warpm = warp >> 2;  // 0..1
    const int warpn = warp & 3;   // 0..3

    const int laneH = (lane & 15) * GH + ((lane >> 4) << 3);

    float acc[4][4][4];
    #pragma unroll
    for (int i = 0; i < 4; i++)
        #pragma unroll
        for (int j = 0; j < 4; j++)
            #pragma unroll
            for (int r = 0; r < 4; r++) acc[i][j][r] = 0.f;

    auto load_stage = [&](int st, int k0) {
        __half* as = dsm + st * GSTH;
        __half* bs = as + 128*GH;
        #pragma unroll
        for (int i = 0; i < 2; i++) {
            int c = tid + i * 256;
            int row = c >> 2, seg = c & 3;
            cpa16(&as[row*GH + seg*8], &A[(size_t)(m0 + row) * K + k0 + seg*8]);
        }
        #pragma unroll
        for (int i = 0; i < 2; i++) {
            int c = tid + i * 256;
            int row = c >> 2, seg = c & 3;
            cpa16(&bs[row*GH + seg*8], &W[(size_t)(n0 + row) * K + k0 + seg*8]);
        }
    };

    const int iters = K / 32;            // 24
    load_stage(0, 0);  CP_COMMIT();
    load_stage(1, 32); CP_COMMIT();

    for (int it = 0; it < iters; ++it) {
        CP_WAIT1();
        __syncthreads();
        if (it + 2 < iters) load_stage((it + 2) % 3, (it + 2) * 32);
        CP_COMMIT();

        const __half* as = dsm + (it % 3) * GSTH;
        const __half* bs = as + 128*GH;

        #pragma unroll
        for (int kc = 0; kc < 2; kc++) {
            int k = kc * 16;
            uint32_t af[4][4];
            #pragma unroll
            for (int ms = 0; ms < 4; ms++)
                ldsm_x4(af[ms][0], af[ms][1], af[ms][2], af[ms][3],
                        as + (warpm*64 + ms*16)*GH + k + laneH);
            #pragma unroll
            for (int nb = 0; nb < 2; nb++) {
                uint32_t b0, b1, b2, b3;
                ldsm_x4(b0, b1, b2, b3,
                        bs + (warpn*32 + nb*16)*GH + k + laneH);
                #pragma unroll
                for (int ms = 0; ms < 4; ms++) {
                    mma_f16(acc[ms][nb*2],   af[ms][0], af[ms][1], af[ms][2],
                            af[ms][3], b0, b2);
                    mma_f16(acc[ms][nb*2+1], af[ms][0], af[ms][1], af[ms][2],
                            af[ms][3], b1, b3);
                }
            }
        }
    }

    #pragma unroll
    for (int ms = 0; ms < 4; ms++) {
        int row0 = m0 + warpm*64 + ms*16 + g;
        int row1 = row0 + 8;
        if (MODE == 2) {
            int b0_ = row0 / SS, s0_ = row0 - b0_*SS;
            int b1_ = row1 / SS, s1_ = row1 - b1_*SS;
            #pragma unroll
            for (int ns = 0; ns < 4; ns++) {
                int col = n0 + warpn*32 + ns*8 + 2*t;
                int h_ = col >> 6, d_ = col & 63;
                float b0v = bias[col], b1v = bias[col + 1];
                size_t base0 = ((size_t)(b0_*HH + h_)*HDD + d_) * SS;
                CH[base0 + s0_]      = __float2half(acc[ms][ns][0] + b0v);
                CH[base0 + SS + s0_] = __float2half(acc[ms][ns][1] + b1v);
                size_t base1 = ((size_t)(b1_*HH + h_)*HDD + d_) * SS;
                CH[base1 + s1_]      = __float2half(acc[ms][ns][2] + b0v);
                CH[base1 + SS + s1_] = __float2half(acc[ms][ns][3] + b1v);
            }
        } else if (MODE == 1) {
            #pragma unroll
            for (int ns = 0; ns < 4; ns++) {
                int col = n0 + warpn*32 + ns*8 + 2*t;
                float b0v = bias[col], b1v = bias[col + 1];
                *(__half2*)&CH[(size_t)row0 * N + col] =
                    __floats2half2_rn(acc[ms][ns][0] + b0v, acc[ms][ns][1] + b1v);
                *(__half2*)&CH[(size_t)row1 * N + col] =
                    __floats2half2_rn(acc[ms][ns][2] + b0v, acc[ms][ns][3] + b1v);
            }
        } else {
            #pragma unroll
            for (int ns = 0; ns < 4; ns++) {
                int col = n0 + warpn*32 + ns*8 + 2*t;
                float b0v = bias[col], b1v = bias[col + 1];
                float2 v0 = {acc[ms][ns][0] + b0v, acc[ms][ns][1] + b1v};
                float2 v1 = {acc[ms][ns][2] + b0v, acc[ms][ns][3] + b1v};
                *(float2*)&C[(size_t)row0 * N + col] = v0;
                *(float2*)&C[(size_t)row1 * N + col] = v1;
            }
        }
    }
}

__global__ __launch_bounds__(256, 2) void gemm_qkv(
    const __half* __restrict__ A,
    const __half* __restrict__ Wq, const __half* __restrict__ Wk,
    const __half* __restrict__ Wv,
    const float* __restrict__ bq, const float* __restrict__ bk,
    const float* __restrict__ bv,
    __half* __restrict__ Qh, __half* __restrict__ Kh, __half* __restrict__ Vt)
{
    int z = blockIdx.z;
    if (z == 0)      gemm_f16<1>(A, Wq, bq, nullptr, Qh, DD, DD);
    else if (z == 1) gemm_f16<1>(A, Wk, bk, nullptr, Kh, DD, DD);
    else             gemm_f16<2>(A, Wv, bv, nullptr, Vt, DD, DD);
}

__global__ __launch_bounds__(256, 2) void gemm_out(
    const __half* __restrict__ A, const __half* __restrict__ W,
    const float* __restrict__ bias, float* __restrict__ C)
{
    gemm_f16<0>(A, W, bias, C, nullptr, DD, DD);
}

// ---------------------------------------------------------------------------
// Fused attention per (b, h, 32-query tile).  ALL fp16 operands, fp32 accum.
// scores: f16 m16n8k16, Q frags hoisted (4 ldsm), K frags via ldmatrix.x2.
// softmax: fp32 in regs from fp16 strip; attn fp32 streaming store.
// AV: f16 m16n8k16 (R14/R15-proven mapping), V fp16 pre-transposed.
// ctx stored fp16.  smem 57344 B -> 3 CTAs/SM.
// ---------------------------------------------------------------------------
#define SQH 72                // Q/K smem row stride (halfs)
#define KVP_H 2560            // kv stage pitch (halfs): max(32*72, 64*40)
#define SCH 584               // strip row stride (halfs)
#define STRV 40               // vT smem row stride (halfs)
#define QROWS 32
#define NSTAGE (SS/32)        // 18
#define RST 72
#define ATTN_SMEM_BYTES ((QROWS*SQH + 3*KVP_H + QROWS*SCH) * 2)   // 57344

__global__ __launch_bounds__(256, 3) void attn_fused(
    const __half* __restrict__ Q, const __half* __restrict__ K,
    const __half* __restrict__ Vt, float* __restrict__ attn,
    __half* __restrict__ ctxh)
{
    extern __shared__ __align__(16) char smemraw[];
    __half* qh  = (__half*)smemraw;            // [32][SQH]
    __half* kvh = qh + QROWS*SQH;              // 3 stage buffers
    __half* ph  = kvh + 3*KVP_H;               // [32][SCH] strip

    const int qt = blockIdx.x, h = blockIdx.y, b = blockIdx.z;
    const int s0 = qt * QROWS;
    const int tid = threadIdx.x;
    const int warp = tid >> 5;
    const int lane = tid & 31;
    const int g = lane >> 2, t = lane & 3;

    const size_t qkbase = (size_t)b * SS * DD + h * HDD;
    const size_t vtbase = (size_t)(b*HH + h) * HDD * SS;

    auto load_q = [&]() {        // 32 rows x 64 halfs: 1 cpa16/thread
        int row = tid >> 3, seg = tid & 7;
        cpa16(&qh[row*SQH + seg*8],
              &Q[qkbase + (size_t)(s0 + row)*DD + seg*8]);
    };
    auto load_k = [&](int st, int kt) {
        __half* dst = kvh + st * KVP_H;
        int row = tid >> 3, seg = tid & 7;
        cpa16(&dst[row*SQH + seg*8],
              &K[qkbase + (size_t)(kt*32 + row)*DD + seg*8]);
    };
    auto load_vt = [&](int st, int kt) {   // 64 dims x 32 tokens
        __half* dst = kvh + st * KVP_H;
        int dim = tid >> 2, seg = tid & 3;
        cpa16(&dst[dim*STRV + seg*8],
              &Vt[vtbase + (size_t)dim*SS + kt*32 + seg*8]);
    };

    load_q();     CP_COMMIT();
    load_k(0, 0); CP_COMMIT();
    load_k(1, 1); CP_COMMIT();

    CP_WAIT2();
    __syncthreads();
    const int warpm = warp >> 2;   // scores: 0..1
    const int warpn = warp & 3;    // scores: 0..3

    // hoist Q fragments: 4 k16-chunks
    const int laneQ = (lane & 15) * SQH + ((lane >> 4) << 3);
    uint32_t qa[4][4];
    #pragma unroll
    for (int kc = 0; kc < 4; kc++)
        ldsm_x4(qa[kc][0], qa[kc][1], qa[kc][2], qa[kc][3],
                qh + (warpm*16)*SQH + kc*16 + laneQ);

    const int laneK2 = ((lane & 7)) * SQH + (((lane >> 3) & 1) << 3);
    const int laneAH = (lane & 15) * SCH + ((lane >> 4) << 3);
    const int laneBH = (lane & 15) * STRV + ((lane >> 4) << 3);

    // ---- scores: f16 mma -> fp16 strip, 18 pipelined stages ----
    for (int kt = 0; kt < NSTAGE; kt++) {
        CP_WAIT1();
        __syncthreads();
        if (kt + 2 < NSTAGE) load_k((kt + 2) % 3, kt + 2);
        CP_COMMIT();

        const __half* ks = kvh + (kt % 3) * KVP_H;
        float acc[4] = {0.f, 0.f, 0.f, 0.f};
        #pragma unroll
        for (int kc = 0; kc < 4; kc++) {
            uint32_t b0, b1;
            ldsm_x2(b0, b1, ks + warpn*8*SQH + kc*16 + laneK2);
            mma_f16(acc, qa[kc][0], qa[kc][1], qa[kc][2], qa[kc][3], b0, b1);
        }

        int row = warpm*16 + g;
        int col = kt*32 + warpn*8 + 2*t;
        *(__half2*)(ph + row*SCH + col) =
            __floats2half2_rn(acc[0]*SCALE, acc[1]*SCALE);
        *(__half2*)(ph + (row+8)*SCH + col) =
            __floats2half2_rn(acc[2]*SCALE, acc[3]*SCALE);
    }
    __syncthreads();

    // prefetch V stages 0,1 -> overlaps softmax
    load_vt(0, 0); CP_COMMIT();
    load_vt(1, 1); CP_COMMIT();

    // ---- softmax: 8 warps x 4 rows, register-resident ----
    #pragma unroll
    for (int rr = 0; rr < 4; rr++) {
        const int r = warp*4 + rr;
        float ev[18];
        #pragma unroll
        for (int jj = 0; jj < 18; jj++)
            ev[jj] = __half2float(ph[r*SCH + lane + 32*jj]);
        float mx = ev[0];
        #pragma unroll
        for (int jj = 1; jj < 18; jj++) mx = fmaxf(mx, ev[jj]);
        #pragma unroll
        for (int o = 16; o; o >>= 1) mx = fmaxf(mx, __shfl_xor_sync(0xffffffffu, mx, o));
        float sum = 0.f;
        #pragma unroll
        for (int jj = 0; jj < 18; jj++) {
            ev[jj] = __expf(ev[jj] - mx);
            sum += ev[jj];
        }
        #pragma unroll
        for (int o = 16; o; o >>= 1) sum += __shfl_xor_sync(0xffffffffu, sum, o);
        float inv = 1.f / sum;
        float* dst = attn + (((size_t)b*HH + h)*SS + s0 + r) * (size_t)SS;
        #pragma unroll
        for (int jj = 0; jj < 18; jj++) {
            float p = ev[jj] * inv;
            __stcs(dst + lane + 32*jj, p);
            ph[r*SCH + lane + 32*jj] = __float2half(p);
        }
    }
    __syncthreads();

    // ---- AV: f16 m16n8k16. warp = (wm: m16, wn: n32, wk: k16-chunk) ----
    const int wm = warp & 1;
    const int wnn = (warp >> 1) & 1;
    const int wkk = (warp >> 2) & 1;

    float acc[4][4];
    #pragma unroll
    for (int j = 0; j < 4; j++)
        #pragma unroll
        for (int r = 0; r < 4; r++) acc[j][r] = 0.f;

    for (int kt = 0; kt < NSTAGE; kt++) {
        CP_WAIT1();
        __syncthreads();
        if (kt + 2 < NSTAGE) load_vt((kt + 2) % 3, kt + 2);
        CP_COMMIT();

        const __half* vh = kvh + (kt % 3) * KVP_H;

        uint32_t a0, a1, a2, a3;
        ldsm_x4(a0, a1, a2, a3,
                ph + wm*16*SCH + kt*32 + wkk*16 + laneAH);
        #pragma unroll
        for (int nblk = 0; nblk < 2; nblk++) {
            uint32_t b0, b1, b2, b3;
            ldsm_x4(b0, b1, b2, b3,
                    vh + (wnn*32 + nblk*16)*STRV + wkk*16 + laneBH);
            mma_f16(acc[nblk*2 + 0], a0, a1, a2, a3, b0, b2);
            mma_f16(acc[nblk*2 + 1], a0, a1, a2, a3, b1, b3);
        }
    }

    // ---- reduce 2 k-partials through smem (strip region reused) ----
    __syncthreads();
    float* red = (float*)ph;   // [2][32][RST] fp32 (18.4 KB < 36.5 KB strip)
    #pragma unroll
    for (int nt = 0; nt < 4; nt++) {
        int col = wnn*32 + nt*8 + 2*t;
        float2 v0 = {acc[nt][0], acc[nt][1]};
        *(float2*)&red[wkk*32*RST + (wm*16 + g)*RST + col] = v0;
        float2 v1 = {acc[nt][2], acc[nt][3]};
        *(float2*)&red[wkk*32*RST + (wm*16 + g + 8)*RST + col] = v1;
    }
    __syncthreads();

    #pragma unroll
    for (int i = 0; i < 2; i++) {
        int f4 = tid + i*256;
        int row = f4 >> 4, c4 = f4 & 15;
        const float* p0 = red + row*RST + c4*4;
        float4 s0v = *(const float4*)(p0);
        float4 s1v = *(const float4*)(p0 + 32*RST);
        size_t idx = ((size_t)(b*SS + s0 + row))*DD + h*HDD + c4*4;
        *(__half2*)&ctxh[idx]     = __floats2half2_rn(s0v.x + s1v.x, s0v.y + s1v.y);
        *(__half2*)&ctxh[idx + 2] = __floats2half2_rn(s0v.z + s1v.z, s0v.w + s1v.w);
    }
}

// ===========================================================================
extern "C" void kernel_launch(void* const* d_in, const int* in_sizes, int n_in,
                              void* d_out, int out_size)
{
    const float* x  = (const float*)d_in[0];
    const float* Wq = (const float*)d_in[1];
    const float* bq = (const float*)d_in[2];
    const float* Wk = (const float*)d_in[3];
    const float* bk = (const float*)d_in[4];
    const float* Wv = (const float*)d_in[5];
    const float* bv = (const float*)d_in[6];
    const float* Wo = (const float*)d_in[7];
    const float* bo = (const float*)d_in[8];

    float* out = (float*)d_out;
    float* attn;
    if (out_size >= OUT_ELEMS + ATTN_ELEMS) {
        attn = out + OUT_ELEMS;
    } else {
        void* p; cudaGetSymbolAddress(&p, g_attn_fallback);
        attn = (float*)p;
    }

    __half *xh, *qh, *kh, *vt, *ctxh, *wqh, *wkh, *wvh, *woh;
    { void* p; cudaGetSymbolAddress(&p, g_xh);   xh   = (__half*)p; }
    { void* p; cudaGetSymbolAddress(&p, g_qh);   qh   = (__half*)p; }
    { void* p; cudaGetSymbolAddress(&p, g_kh);   kh   = (__half*)p; }
    { void* p; cudaGetSymbolAddress(&p, g_vt);   vt   = (__half*)p; }
    { void* p; cudaGetSymbolAddress(&p, g_ctxh); ctxh = (__half*)p; }
    { void* p; cudaGetSymbolAddress(&p, g_wqh);  wqh  = (__half*)p; }
    { void* p; cudaGetSymbolAddress(&p, g_wkh);  wkh  = (__half*)p; }
    { void* p; cudaGetSymbolAddress(&p, g_wvh);  wvh  = (__half*)p; }
    { void* p; cudaGetSymbolAddress(&p, g_woh);  woh  = (__half*)p; }

    const int gemm_smem = 3 * GSTH * 2;                          // 61440
    cudaFuncSetAttribute(gemm_qkv,
                         cudaFuncAttributeMaxDynamicSharedMemorySize, gemm_smem);
    cudaFuncSetAttribute(gemm_out,
                         cudaFuncAttributeMaxDynamicSharedMemorySize, gemm_smem);
    cudaFuncSetAttribute(attn_fused,
                         cudaFuncAttributeMaxDynamicSharedMemorySize, ATTN_SMEM_BYTES);

    // 1) fp16 conversion of x and all four W
    tohalf_kernel<<<1184, 256>>>(x, xh, OUT_ELEMS/4);
    dim3 gW(288, 4);
    tohalf_w4_kernel<<<gW, 256>>>(Wq, Wk, Wv, Wo, wqh, wkh, wvh, woh, (DD*DD)/4);

    // 2) fused Q/K/V projections (Q,K fp16 row-major; V fp16 transposed)
    dim3 gQKV(DD/128, MTOK/128, 3);
    gemm_qkv<<<gQKV, 256, gemm_smem>>>(xh, wqh, wkh, wvh, bq, bk, bv,
                                       qh, kh, vt);

    // 3) fused scores + softmax + AV (3 CTAs/SM)
    dim3 gAttn(SS/QROWS, HH, BB);         // (18, 12, 32)
    attn_fused<<<gAttn, 256, ATTN_SMEM_BYTES>>>(qh, kh, vt, attn, ctxh);

    // 4) output projection (fp32 out)
    dim3 gO(DD/128, MTOK/128);
    gemm_out<<<gO, 256, gemm_smem>>>(ctxh, woh, bo, out);
}

// round 17
// speedup vs baseline: 1.6569x; 1.1032x over previous
#include <cuda_runtime.h>
#include <cuda_fp16.h>
#include <cstdint>
#include <cstddef>

#define BB 32
#define SS 576
#define DD 768
#define HH 12
#define HDD 64
#define MTOK (BB*SS)               // 18432
#define OUT_ELEMS (BB*SS*DD)       // 14155776
#define ATTN_ELEMS (BB*HH*SS*SS)   // 127401984
#define SCALE 0.125f

// ---- scratch (static device globals; no runtime allocation) ----
__device__ __half g_xh[OUT_ELEMS];            // fp16 x
__device__ __half g_qh[OUT_ELEMS];            // fp16 Q [b][s][d]
__device__ __half g_kh[OUT_ELEMS];            // fp16 K [b][s][d]
__device__ __half g_vt[OUT_ELEMS];            // fp16 V transposed [b][h][dim][tok]
__device__ __half g_ctxh[OUT_ELEMS];          // fp16 ctx
__device__ __half g_wqh[DD*DD], g_wkh[DD*DD], g_wvh[DD*DD], g_woh[DD*DD];
__device__ float g_attn_fallback[ATTN_ELEMS];

// ---------------------------------------------------------------------------
__device__ __forceinline__ void mma_f16(float c[4],
    uint32_t a0, uint32_t a1, uint32_t a2, uint32_t a3,
    uint32_t b0, uint32_t b1)
{
    asm volatile(
        "mma.sync.aligned.m16n8k16.row.col.f32.f16.f16.f32 "
        "{%0,%1,%2,%3}, {%4,%5,%6,%7}, {%8,%9}, {%0,%1,%2,%3};"
        : "+f"(c[0]), "+f"(c[1]), "+f"(c[2]), "+f"(c[3])
        : "r"(a0), "r"(a1), "r"(a2), "r"(a3), "r"(b0), "r"(b1));
}

__device__ __forceinline__ void ldsm_x4(uint32_t& r0, uint32_t& r1,
                                        uint32_t& r2, uint32_t& r3,
                                        const void* p)
{
    uint32_t a = (uint32_t)__cvta_generic_to_shared(p);
    asm volatile("ldmatrix.sync.aligned.m8n8.x4.shared.b16 {%0,%1,%2,%3}, [%4];"
                 : "=r"(r0), "=r"(r1), "=r"(r2), "=r"(r3) : "r"(a));
}

__device__ __forceinline__ void ldsm_x2(uint32_t& r0, uint32_t& r1,
                                        const void* p)
{
    uint32_t a = (uint32_t)__cvta_generic_to_shared(p);
    asm volatile("ldmatrix.sync.aligned.m8n8.x2.shared.b16 {%0,%1}, [%2];"
                 : "=r"(r0), "=r"(r1) : "r"(a));
}

__device__ __forceinline__ void cpa16(void* dst, const void* src) {
    uint32_t d = (uint32_t)__cvta_generic_to_shared(dst);
    asm volatile("cp.async.cg.shared.global [%0], [%1], 16;\n"
                 :: "r"(d), "l"(src));
}
#define CP_COMMIT() asm volatile("cp.async.commit_group;\n" ::)
#define CP_WAIT1()  asm volatile("cp.async.wait_group 1;\n" ::)
#define CP_WAIT2()  asm volatile("cp.async.wait_group 2;\n" ::)

// ---------------------------------------------------------------------------
// fp32 -> fp16 conversion passes
__global__ void tohalf_kernel(const float* __restrict__ in,
                              __half* __restrict__ out, int n4)
{
    for (int i = blockIdx.x * blockDim.x + threadIdx.x; i < n4;
         i += gridDim.x * blockDim.x) {
        float4 v = ((const float4*)in)[i];
        *(__half2*)&out[i*4]     = __floats2half2_rn(v.x, v.y);
        *(__half2*)&out[i*4 + 2] = __floats2half2_rn(v.z, v.w);
    }
}

__global__ void tohalf_w4_kernel(
    const float* __restrict__ w0, const float* __restrict__ w1,
    const float* __restrict__ w2, const float* __restrict__ w3,
    __half* __restrict__ o0, __half* __restrict__ o1,
    __half* __restrict__ o2, __half* __restrict__ o3, int n4)
{
    int z = blockIdx.y;
    const float* in = (z == 0) ? w0 : (z == 1) ? w1 : (z == 2) ? w2 : w3;
    __half* out     = (z == 0) ? o0 : (z == 1) ? o1 : (z == 2) ? o2 : o3;
    for (int i = blockIdx.x * blockDim.x + threadIdx.x; i < n4;
         i += gridDim.x * blockDim.x) {
        float4 v = ((const float4*)in)[i];
        *(__half2*)&out[i*4]     = __floats2half2_rn(v.x, v.y);
        *(__half2*)&out[i*4 + 2] = __floats2half2_rn(v.z, v.w);
    }
}

// ---------------------------------------------------------------------------
// fp16 GEMM: C = A[M,K] @ W^T + bias.  A,W fp16; accum fp32.
// MODE 0: fp32 C.  MODE 1: fp16 row-major CH (Q,K).  MODE 2: fp16 transposed VT.
// BM=128, BN=128, BK=64 halfs (12 iters), f16 m16n8k16,
// 3-stage cp.async pipeline, one __syncthreads per iteration.
// smem: 3 stages x 2 x 128 x 72 halfs = 110592 B -> 2 CTAs/SM.
// ---------------------------------------------------------------------------
#define GH 72                // smem row stride (halfs)
#define GSTH (2*128*GH)      // halfs per stage

template <int MODE>
__device__ __forceinline__ void gemm_f16(
    const __half* __restrict__ A, const __half* __restrict__ W,
    const float* __restrict__ bias, float* __restrict__ C,
    __half* __restrict__ CH, int N, int K)
{
    extern __shared__ __align__(16) char dsmraw[];
    __half* dsm = (__half*)dsmraw;

    const int tid = threadIdx.x;
    const int m0 = blockIdx.y * 128;
    const int n0 = blockIdx.x * 128;
    const int warp = tid >> 5;
    const int lane = tid & 31;
    const int g = lane >> 2;
    const int t = lane & 3;
    const int warpm = warp >> 2;  // 0..1
    const int warpn = warp & 3;   // 0..3

    const int laneH = (lane & 15) * GH + ((lane >> 4) << 3);

    float acc[4][4][4];
    #pragma unroll
    for (int i = 0; i < 4; i++)
        #pragma unroll
        for (int j = 0; j < 4; j++)
            #pragma unroll
            for (int r = 0; r < 4; r++) acc[i][j][r] = 0.f;

    auto load_stage = [&](int st, int k0) {
        __half* as = dsm + st * GSTH;
        __half* bs = as + 128*GH;
        #pragma unroll
        for (int i = 0; i < 4; i++) {
            int c = tid + i * 256;
            int row = c >> 3, seg = c & 7;
            cpa16(&as[row*GH + seg*8], &A[(size_t)(m0 + row) * K + k0 + seg*8]);
        }
        #pragma unroll
        for (int i = 0; i < 4; i++) {
            int c = tid + i * 256;
            int row = c >> 3, seg = c & 7;
            cpa16(&bs[row*GH + seg*8], &W[(size_t)(n0 + row) * K + k0 + seg*8]);
        }
    };

    const int iters = K / 64;            // 12
    load_stage(0, 0);  CP_COMMIT();
    load_stage(1, 64); CP_COMMIT();

    for (int it = 0; it < iters; ++it) {
        CP_WAIT1();
        __syncthreads();
        if (it + 2 < iters) load_stage((it + 2) % 3, (it + 2) * 64);
        CP_COMMIT();

        const __half* as = dsm + (it % 3) * GSTH;
        const __half* bs = as + 128*GH;

        #pragma unroll
        for (int kc = 0; kc < 4; kc++) {
            int k = kc * 16;
            uint32_t af[4][4];
            #pragma unroll
            for (int ms = 0; ms < 4; ms++)
                ldsm_x4(af[ms][0], af[ms][1], af[ms][2], af[ms][3],
                        as + (warpm*64 + ms*16)*GH + k + laneH);
            #pragma unroll
            for (int nb = 0; nb < 2; nb++) {
                uint32_t b0, b1, b2, b3;
                ldsm_x4(b0, b1, b2, b3,
                        bs + (warpn*32 + nb*16)*GH + k + laneH);
                #pragma unroll
                for (int ms = 0; ms < 4; ms++) {
                    mma_f16(acc[ms][nb*2],   af[ms][0], af[ms][1], af[ms][2],
                            af[ms][3], b0, b2);
                    mma_f16(acc[ms][nb*2+1], af[ms][0], af[ms][1], af[ms][2],
                            af[ms][3], b1, b3);
                }
            }
        }
    }

    #pragma unroll
    for (int ms = 0; ms < 4; ms++) {
        int row0 = m0 + warpm*64 + ms*16 + g;
        int row1 = row0 + 8;
        if (MODE == 2) {
            int b0_ = row0 / SS, s0_ = row0 - b0_*SS;
            int b1_ = row1 / SS, s1_ = row1 - b1_*SS;
            #pragma unroll
            for (int ns = 0; ns < 4; ns++) {
                int col = n0 + warpn*32 + ns*8 + 2*t;
                int h_ = col >> 6, d_ = col & 63;
                float b0v = bias[col], b1v = bias[col + 1];
                size_t base0 = ((size_t)(b0_*HH + h_)*HDD + d_) * SS;
                CH[base0 + s0_]      = __float2half(acc[ms][ns][0] + b0v);
                CH[base0 + SS + s0_] = __float2half(acc[ms][ns][1] + b1v);
                size_t base1 = ((size_t)(b1_*HH + h_)*HDD + d_) * SS;
                CH[base1 + s1_]      = __float2half(acc[ms][ns][2] + b0v);
                CH[base1 + SS + s1_] = __float2half(acc[ms][ns][3] + b1v);
            }
        } else if (MODE == 1) {
            #pragma unroll
            for (int ns = 0; ns < 4; ns++) {
                int col = n0 + warpn*32 + ns*8 + 2*t;
                float b0v = bias[col], b1v = bias[col + 1];
                *(__half2*)&CH[(size_t)row0 * N + col] =
                    __floats2half2_rn(acc[ms][ns][0] + b0v, acc[ms][ns][1] + b1v);
                *(__half2*)&CH[(size_t)row1 * N + col] =
                    __floats2half2_rn(acc[ms][ns][2] + b0v, acc[ms][ns][3] + b1v);
            }
        } else {
            #pragma unroll
            for (int ns = 0; ns < 4; ns++) {
                int col = n0 + warpn*32 + ns*8 + 2*t;
                float b0v = bias[col], b1v = bias[col + 1];
                float2 v0 = {acc[ms][ns][0] + b0v, acc[ms][ns][1] + b1v};
                float2 v1 = {acc[ms][ns][2] + b0v, acc[ms][ns][3] + b1v};
                *(float2*)&C[(size_t)row0 * N + col] = v0;
                *(float2*)&C[(size_t)row1 * N + col] = v1;
            }
        }
    }
}

__global__ __launch_bounds__(256, 2) void gemm_qkv(
    const __half* __restrict__ A,
    const __half* __restrict__ Wq, const __half* __restrict__ Wk,
    const __half* __restrict__ Wv,
    const float* __restrict__ bq, const float* __restrict__ bk,
    const float* __restrict__ bv,
    __half* __restrict__ Qh, __half* __restrict__ Kh, __half* __restrict__ Vt)
{
    int z = blockIdx.z;
    if (z == 0)      gemm_f16<1>(A, Wq, bq, nullptr, Qh, DD, DD);
    else if (z == 1) gemm_f16<1>(A, Wk, bk, nullptr, Kh, DD, DD);
    else             gemm_f16<2>(A, Wv, bv, nullptr, Vt, DD, DD);
}

__global__ __launch_bounds__(256, 2) void gemm_out(
    const __half* __restrict__ A, const __half* __restrict__ W,
    const float* __restrict__ bias, float* __restrict__ C)
{
    gemm_f16<0>(A, W, bias, C, nullptr, DD, DD);
}

// ---------------------------------------------------------------------------
// Fused attention per (b, h, 32-query tile).  ALL fp16 operands, fp32 accum.
// 64-key score stages and 64-token V stages (9 stages each; inner 2x32 halves).
// smem: qh 32x72 + 3x(64x72) + strip 32x584 = 69632 B -> 3 CTAs/SM.
// ---------------------------------------------------------------------------
#define SQH 72                // Q/K smem row stride (halfs)
#define KVP_H (64*72)         // kv stage pitch (halfs) = 4608
#define SCH 584               // strip row stride (halfs)
#define QROWS 32
#define NST64A (SS/64)        // 9
#define RST 72
#define ATTN_SMEM_BYTES ((QROWS*SQH + 3*KVP_H + QROWS*SCH) * 2)   // 69632

__global__ __launch_bounds__(256, 3) void attn_fused(
    const __half* __restrict__ Q, const __half* __restrict__ K,
    const __half* __restrict__ Vt, float* __restrict__ attn,
    __half* __restrict__ ctxh)
{
    extern __shared__ __align__(16) char smemraw[];
    __half* qh  = (__half*)smemraw;            // [32][SQH]
    __half* kvh = qh + QROWS*SQH;              // 3 stage buffers (64 rows x 72)
    __half* ph  = kvh + 3*KVP_H;               // [32][SCH] strip

    const int qt = blockIdx.x, h = blockIdx.y, b = blockIdx.z;
    const int s0 = qt * QROWS;
    const int tid = threadIdx.x;
    const int warp = tid >> 5;
    const int lane = tid & 31;
    const int g = lane >> 2, t = lane & 3;

    const size_t qkbase = (size_t)b * SS * DD + h * HDD;
    const size_t vtbase = (size_t)(b*HH + h) * HDD * SS;

    auto load_q = [&]() {        // 32 rows x 64 halfs: 1 cpa16/thread
        int row = tid >> 3, seg = tid & 7;
        cpa16(&qh[row*SQH + seg*8],
              &Q[qkbase + (size_t)(s0 + row)*DD + seg*8]);
    };
    auto load_k = [&](int st, int kt) {   // 64 keys x 64 halfs: 2/thread
        __half* dst = kvh + st * KVP_H;
        #pragma unroll
        for (int i = 0; i < 2; i++) {
            int c = tid + i*256;
            int row = c >> 3, seg = c & 7;
            cpa16(&dst[row*SQH + seg*8],
                  &K[qkbase + (size_t)(kt*64 + row)*DD + seg*8]);
        }
    };
    auto load_vt = [&](int st, int kt) {  // 64 dims x 64 tokens: 2/thread
        __half* dst = kvh + st * KVP_H;
        #pragma unroll
        for (int i = 0; i < 2; i++) {
            int c = tid + i*256;
            int dim = c >> 3, seg = c & 7;
            cpa16(&dst[dim*SQH + seg*8],
                  &Vt[vtbase + (size_t)dim*SS + kt*64 + seg*8]);
        }
    };

    load_q();     CP_COMMIT();
    load_k(0, 0); CP_COMMIT();
    load_k(1, 1); CP_COMMIT();

    CP_WAIT2();
    __syncthreads();
    const int warpm = warp >> 2;   // scores: 0..1
    const int warpn = warp & 3;    // scores: 0..3

    // hoist Q fragments: 4 k16-chunks
    const int laneQ = (lane & 15) * SQH + ((lane >> 4) << 3);
    uint32_t qa[4][4];
    #pragma unroll
    for (int kc = 0; kc < 4; kc++)
        ldsm_x4(qa[kc][0], qa[kc][1], qa[kc][2], qa[kc][3],
                qh + (warpm*16)*SQH + kc*16 + laneQ);

    const int laneK2 = ((lane & 7)) * SQH + (((lane >> 3) & 1) << 3);
    const int laneAH = (lane & 15) * SCH + ((lane >> 4) << 3);
    const int laneBH = (lane & 15) * SQH + ((lane >> 4) << 3);

    // ---- scores: 9 x 64-key stages; inner 2 x 32-key halves ----
    for (int kt = 0; kt < NST64A; kt++) {
        CP_WAIT1();
        __syncthreads();
        if (kt + 2 < NST64A) load_k((kt + 2) % 3, kt + 2);
        CP_COMMIT();

        const __half* ks = kvh + (kt % 3) * KVP_H;
        #pragma unroll
        for (int hf = 0; hf < 2; hf++) {
            float acc[4] = {0.f, 0.f, 0.f, 0.f};
            #pragma unroll
            for (int kc = 0; kc < 4; kc++) {
                uint32_t b0, b1;
                ldsm_x2(b0, b1,
                        ks + (hf*32 + warpn*8)*SQH + kc*16 + laneK2);
                mma_f16(acc, qa[kc][0], qa[kc][1], qa[kc][2], qa[kc][3],
                        b0, b1);
            }
            int row = warpm*16 + g;
            int col = kt*64 + hf*32 + warpn*8 + 2*t;
            *(__half2*)(ph + row*SCH + col) =
                __floats2half2_rn(acc[0]*SCALE, acc[1]*SCALE);
            *(__half2*)(ph + (row+8)*SCH + col) =
                __floats2half2_rn(acc[2]*SCALE, acc[3]*SCALE);
        }
    }
    __syncthreads();

    // prefetch V stages 0,1 -> overlaps softmax
    load_vt(0, 0); CP_COMMIT();
    load_vt(1, 1); CP_COMMIT();

    // ---- softmax: 8 warps x 4 rows, register-resident ----
    #pragma unroll
    for (int rr = 0; rr < 4; rr++) {
        const int r = warp*4 + rr;
        float ev[18];
        #pragma unroll
        for (int jj = 0; jj < 18; jj++)
            ev[jj] = __half2float(ph[r*SCH + lane + 32*jj]);
        float mx = ev[0];
        #pragma unroll
        for (int jj = 1; jj < 18; jj++) mx = fmaxf(mx, ev[jj]);
        #pragma unroll
        for (int o = 16; o; o >>= 1) mx = fmaxf(mx, __shfl_xor_sync(0xffffffffu, mx, o));
        float sum = 0.f;
        #pragma unroll
        for (int jj = 0; jj < 18; jj++) {
            ev[jj] = __expf(ev[jj] - mx);
            sum += ev[jj];
        }
        #pragma unroll
        for (int o = 16; o; o >>= 1) sum += __shfl_xor_sync(0xffffffffu, sum, o);
        float inv = 1.f / sum;
        float* dst = attn + (((size_t)b*HH + h)*SS + s0 + r) * (size_t)SS;
        #pragma unroll
        for (int jj = 0; jj < 18; jj++) {
            float p = ev[jj] * inv;
            __stcs(dst + lane + 32*jj, p);
            ph[r*SCH + lane + 32*jj] = __float2half(p);
        }
    }
    __syncthreads();

    // ---- AV: f16 m16n8k16, 9 x 64-token stages; inner 2 x 32 halves ----
    const int wm = warp & 1;
    const int wnn = (warp >> 1) & 1;
    const int wkk = (warp >> 2) & 1;

    float acc[4][4];
    #pragma unroll
    for (int j = 0; j < 4; j++)
        #pragma unroll
        for (int r = 0; r < 4; r++) acc[j][r] = 0.f;

    for (int kt = 0; kt < NST64A; kt++) {
        CP_WAIT1();
        __syncthreads();
        if (kt + 2 < NST64A) load_vt((kt + 2) % 3, kt + 2);
        CP_COMMIT();

        const __half* vh = kvh + (kt % 3) * KVP_H;
        #pragma unroll
        for (int hf = 0; hf < 2; hf++) {
            const int k = hf*32 + wkk*16;
            uint32_t a0, a1, a2, a3;
            ldsm_x4(a0, a1, a2, a3,
                    ph + wm*16*SCH + kt*64 + k + laneAH);
            #pragma unroll
            for (int nblk = 0; nblk < 2; nblk++) {
                uint32_t b0, b1, b2, b3;
                ldsm_x4(b0, b1, b2, b3,
                        vh + (wnn*32 + nblk*16)*SQH + k + laneBH);
                mma_f16(acc[nblk*2 + 0], a0, a1, a2, a3, b0, b2);
                mma_f16(acc[nblk*2 + 1], a0, a1, a2, a3, b1, b3);
            }
        }
    }

    // ---- reduce 2 k-partials through smem (strip region reused) ----
    __syncthreads();
    float* red = (float*)ph;   // [2][32][RST] fp32 (18.4 KB < strip)
    #pragma unroll
    for (int nt = 0; nt < 4; nt++) {
        int col = wnn*32 + nt*8 + 2*t;
        float2 v0 = {acc[nt][0], acc[nt][1]};
        *(float2*)&red[wkk*32*RST + (wm*16 + g)*RST + col] = v0;
        float2 v1 = {acc[nt][2], acc[nt][3]};
        *(float2*)&red[wkk*32*RST + (wm*16 + g + 8)*RST + col] = v1;
    }
    __syncthreads();

    #pragma unroll
    for (int i = 0; i < 2; i++) {
        int f4 = tid + i*256;
        int row = f4 >> 4, c4 = f4 & 15;
        const float* p0 = red + row*RST + c4*4;
        float4 s0v = *(const float4*)(p0);
        float4 s1v = *(const float4*)(p0 + 32*RST);
        size_t idx = ((size_t)(b*SS + s0 + row))*DD + h*HDD + c4*4;
        *(__half2*)&ctxh[idx]     = __floats2half2_rn(s0v.x + s1v.x, s0v.y + s1v.y);
        *(__half2*)&ctxh[idx + 2] = __floats2half2_rn(s0v.z + s1v.z, s0v.w + s1v.w);
    }
}

// ===========================================================================
extern "C" void kernel_launch(void* const* d_in, const int* in_sizes, int n_in,
                              void* d_out, int out_size)
{
    const float* x  = (const float*)d_in[0];
    const float* Wq = (const float*)d_in[1];
    const float* bq = (const float*)d_in[2];
    const float* Wk = (const float*)d_in[3];
    const float* bk = (const float*)d_in[4];
    const float* Wv = (const float*)d_in[5];
    const float* bv = (const float*)d_in[6];
    const float* Wo = (const float*)d_in[7];
    const float* bo = (const float*)d_in[8];

    float* out = (float*)d_out;
    float* attn;
    if (out_size >= OUT_ELEMS + ATTN_ELEMS) {
        attn = out + OUT_ELEMS;
    } else {
        void* p; cudaGetSymbolAddress(&p, g_attn_fallback);
        attn = (float*)p;
    }

    __half *xh, *qh, *kh, *vt, *ctxh, *wqh, *wkh, *wvh, *woh;
    { void* p; cudaGetSymbolAddress(&p, g_xh);   xh   = (__half*)p; }
    { void* p; cudaGetSymbolAddress(&p, g_qh);   qh   = (__half*)p; }
    { void* p; cudaGetSymbolAddress(&p, g_kh);   kh   = (__half*)p; }
    { void* p; cudaGetSymbolAddress(&p, g_vt);   vt   = (__half*)p; }
    { void* p; cudaGetSymbolAddress(&p, g_ctxh); ctxh = (__half*)p; }
    { void* p; cudaGetSymbolAddress(&p, g_wqh);  wqh  = (__half*)p; }
    { void* p; cudaGetSymbolAddress(&p, g_wkh);  wkh  = (__half*)p; }
    { void* p; cudaGetSymbolAddress(&p, g_wvh);  wvh  = (__half*)p; }
    { void* p; cudaGetSymbolAddress(&p, g_woh);  woh  = (__half*)p; }

    const int gemm_smem = 3 * GSTH * 2;                          // 110592
    cudaFuncSetAttribute(gemm_qkv,
                         cudaFuncAttributeMaxDynamicSharedMemorySize, gemm_smem);
    cudaFuncSetAttribute(gemm_out,
                         cudaFuncAttributeMaxDynamicSharedMemorySize, gemm_smem);
    cudaFuncSetAttribute(attn_fused,
                         cudaFuncAttributeMaxDynamicSharedMemorySize, ATTN_SMEM_BYTES);

    // 1) fp16 conversion of x and all four W
    tohalf_kernel<<<1184, 256>>>(x, xh, OUT_ELEMS/4);
    dim3 gW(288, 4);
    tohalf_w4_kernel<<<gW, 256>>>(Wq, Wk, Wv, Wo, wqh, wkh, wvh, woh, (DD*DD)/4);

    // 2) fused Q/K/V projections (Q,K fp16 row-major; V fp16 transposed)
    dim3 gQKV(DD/128, MTOK/128, 3);
    gemm_qkv<<<gQKV, 256, gemm_smem>>>(xh, wqh, wkh, wvh, bq, bk, bv,
                                       qh, kh, vt);

    // 3) fused scores + softmax + AV (3 CTAs/SM)
    dim3 gAttn(SS/QROWS, HH, BB);         // (18, 12, 32)
    attn_fused<<<gAttn, 256, ATTN_SMEM_BYTES>>>(qh, kh, vt, attn, ctxh);

    // 4) output projection (fp32 out)
    dim3 gO(DD/128, MTOK/128);
    gemm_out<<<gO, 256, gemm_smem>>>(ctxh, woh, bo, out);
}